// round 1
// baseline (speedup 1.0000x reference)
#include <cuda_runtime.h>
#include <math.h>

// Problem constants: x (8,3,128,128) f32, mask unused, conv_w (128,128) f32.
// Output (8,129,128,128) f32.
#define BZ   8
#define IM   128
#define HW   (IM * IM)          // 16384
#define CIN  3

// Scratch for S[b,i,w] = (1/128)|DFT_h(img[:,w])[i]|
__device__ float g_S[BZ * IM * IM];

// ---------------------------------------------------------------------------
// Kernel A: column DFT magnitude.
// grid = (128 w, 8 b), block = 128 threads (i).
// ---------------------------------------------------------------------------
__global__ void __launch_bounds__(IM) dft_mag_kernel(const float* __restrict__ x) {
    const int w   = blockIdx.x;
    const int b   = blockIdx.y;
    const int tid = threadIdx.x;

    __shared__ float re[IM], im_[IM], cs[IM], sn[IM];

    const float* xb = x + (size_t)b * CIN * HW;
    re[tid]  = xb[tid * IM + w];            // channel 0, row tid, col w
    im_[tid] = xb[HW + tid * IM + w];       // channel 1

    // twiddle table: e^{-2*pi*i*k/128} for k=0..127
    float ang = -6.283185307179586f * (float)tid * (1.0f / 128.0f);
    sincosf(ang, &sn[tid], &cs[tid]);
    __syncthreads();

    const int i = tid;
    float sr = 0.0f, si = 0.0f;
#pragma unroll 8
    for (int h = 0; h < IM; h++) {
        int   k = (i * h) & (IM - 1);
        float c = cs[k], s = sn[k];
        float r = re[h], m = im_[h];
        sr = fmaf(r, c, sr); sr = fmaf(-m, s, sr);
        si = fmaf(r, s, si); si = fmaf( m, c, si);
    }
    g_S[b * HW + i * IM + w] = sqrtf(sr * sr + si * si) * (1.0f / 128.0f);
}

// ---------------------------------------------------------------------------
// Kernel B: E = leakyrelu(conv_w @ S), broadcast over h into output; o==128
// copies channel 2 of x.
// grid = (129 o, 8 b), block = 128 threads (w).
// ---------------------------------------------------------------------------
__global__ void __launch_bounds__(IM) embed_bcast_kernel(const float* __restrict__ x,
                                                         const float* __restrict__ conv_w,
                                                         float* __restrict__ out) {
    const int o   = blockIdx.x;     // 0..128
    const int b   = blockIdx.y;
    const int tid = threadIdx.x;    // w

    float4* out4 = (float4*)(out + (size_t)(b * (IM + 1) + o) * HW);

    if (o == IM) {
        // passthrough channel: x[b,2,:,:]
        const float4* src = (const float4*)(x + (size_t)b * CIN * HW + 2 * HW);
#pragma unroll 4
        for (int j = tid; j < HW / 4; j += IM) out4[j] = src[j];
        return;
    }

    __shared__ float e_sh[IM];
    const float* S    = g_S + b * HW;
    const float* Wrow = conv_w + o * IM;

    float acc = 0.0f;
#pragma unroll 8
    for (int c = 0; c < IM; c++) acc = fmaf(__ldg(&Wrow[c]), S[c * IM + tid], acc);

    e_sh[tid] = (acc >= 0.0f) ? acc : 0.2f * acc;
    __syncthreads();

    const float4* e4 = (const float4*)e_sh;
#pragma unroll 4
    for (int j = tid; j < HW / 4; j += IM) {
        out4[j] = e4[j & (IM / 4 - 1)];     // h = j/32, w4 = j%32, E indep of h
    }
}

// ---------------------------------------------------------------------------
extern "C" void kernel_launch(void* const* d_in, const int* in_sizes, int n_in,
                              void* d_out, int out_size) {
    const float* x      = (const float*)d_in[0];
    const float* conv_w = (const float*)d_in[2];
    float*       out    = (float*)d_out;

    dft_mag_kernel<<<dim3(IM, BZ), IM>>>(x);
    embed_bcast_kernel<<<dim3(IM + 1, BZ), IM>>>(x, conv_w, out);
}

// round 2
// speedup vs baseline: 1.2620x; 1.2620x over previous
#include <cuda_runtime.h>
#include <math.h>

#define BZ   8
#define IM   128
#define HW   (IM * IM)          // 16384
#define CIN  3

// Scratch: S[b][i][w] = (1/128)|DFT_h(img[:,w])[i]|,  E[b][o][w] = leakyrelu(W@S)
__device__ float g_S[BZ * IM * IM];
__device__ float g_E[BZ * IM * IM];

// ---------------------------------------------------------------------------
// Kernel A: radix-4 column DFT magnitude.
// grid = (32 wgroups, 8 b), block = 128 threads = 4 warps = 4 columns.
// Thread lane i computes outputs i, i+32, i+64, i+96 for its column.
// ---------------------------------------------------------------------------
__global__ void __launch_bounds__(128) dft_kernel(const float* __restrict__ x) {
    const int b    = blockIdx.y;
    const int w0   = blockIdx.x * 4;
    const int tid  = threadIdx.x;
    const int wl   = tid >> 5;         // warp -> column
    const int lane = tid & 31;         // i

    __shared__ float sRe[4][IM], sIm[4][IM];

    // Load 4 columns (float4 per row, w0 is 4-aligned), both channels.
    const float* xb = x + (size_t)b * CIN * HW;
    for (int k = tid; k < 256; k += 128) {
        int ch = k >> 7, h = k & 127;
        float4 v = ((const float4*)(xb + (size_t)ch * HW))[h * (IM / 4) + (w0 >> 2)];
        float (*dst)[IM] = ch ? sIm : sRe;
        dst[0][h] = v.x; dst[1][h] = v.y; dst[2][h] = v.z; dst[3][h] = v.w;
    }
    __syncthreads();

    // Rotation step e^{-2*pi*i*lane/32}
    float s0, c0;
    sincosf(-6.283185307179586f * (float)lane * (1.0f / 32.0f), &s0, &c0);
    float cr = 1.0f, ci = 0.0f;

    float A0r = 0, A0i = 0, A1r = 0, A1i = 0, A2r = 0, A2i = 0, A3r = 0, A3i = 0;
    const float4* r4 = (const float4*)sRe[wl];
    const float4* m4 = (const float4*)sIm[wl];

#pragma unroll
    for (int t = 0; t < 32; t++) {
        float4 xr = r4[t];     // samples 4t .. 4t+3 (broadcast across warp)
        float4 xm = m4[t];
        A0r = fmaf(xr.x, cr, A0r); A0r = fmaf(-xm.x, ci, A0r);
        A0i = fmaf(xr.x, ci, A0i); A0i = fmaf( xm.x, cr, A0i);
        A1r = fmaf(xr.y, cr, A1r); A1r = fmaf(-xm.y, ci, A1r);
        A1i = fmaf(xr.y, ci, A1i); A1i = fmaf( xm.y, cr, A1i);
        A2r = fmaf(xr.z, cr, A2r); A2r = fmaf(-xm.z, ci, A2r);
        A2i = fmaf(xr.z, ci, A2i); A2i = fmaf( xm.z, cr, A2i);
        A3r = fmaf(xr.w, cr, A3r); A3r = fmaf(-xm.w, ci, A3r);
        A3i = fmaf(xr.w, ci, A3i); A3i = fmaf( xm.w, cr, A3i);
        float nr = cr * c0 - ci * s0;
        float ni = cr * s0 + ci * c0;
        cr = nr; ci = ni;
    }

    // Twiddles W^lane, W^2lane, W^3lane with W = e^{-2*pi*i/128}
    float sw, cw;
    sincosf(-6.283185307179586f * (float)lane * (1.0f / 128.0f), &sw, &cw);
    float c2 = cw * cw - sw * sw, s2 = 2.0f * cw * sw;
    float c3 = c2 * cw - s2 * sw, s3 = c2 * sw + s2 * cw;

    float T0r = A0r,                T0i = A0i;
    float T1r = cw * A1r - sw * A1i, T1i = cw * A1i + sw * A1r;
    float T2r = c2 * A2r - s2 * A2i, T2i = c2 * A2i + s2 * A2r;
    float T3r = c3 * A3r - s3 * A3i, T3i = c3 * A3i + s3 * A3r;

    float Er = T0r + T2r, Ei = T0i + T2i;
    float Fr = T1r + T3r, Fi = T1i + T3i;
    float Gr = T0r - T2r, Gi = T0i - T2i;
    float Hr = T1r - T3r, Hi = T1i - T3i;

    // S_i = E+F ; S_{i+64} = E-F ; S_{i+32} = G - iH ; S_{i+96} = G + iH
    float m0r = Er + Fr, m0i = Ei + Fi;
    float m2r = Er - Fr, m2i = Ei - Fi;
    float m1r = Gr + Hi, m1i = Gi - Hr;
    float m3r = Gr - Hi, m3i = Gi + Hr;

    const float inv = 1.0f / 128.0f;
    float* Sb = g_S + b * HW + (w0 + wl);
    Sb[(lane      ) * IM] = sqrtf(m0r * m0r + m0i * m0i) * inv;
    Sb[(lane +  32) * IM] = sqrtf(m1r * m1r + m1i * m1i) * inv;
    Sb[(lane +  64) * IM] = sqrtf(m2r * m2r + m2i * m2i) * inv;
    Sb[(lane +  96) * IM] = sqrtf(m3r * m3r + m3i * m3i) * inv;
}

// ---------------------------------------------------------------------------
// Kernel B1: E[b,o,w] = leakyrelu( sum_c W[o,c] * S[b,c,w] )
// grid = (128 o, 8 b), block = 128 threads (w).
// ---------------------------------------------------------------------------
__global__ void __launch_bounds__(IM) gemm_kernel(const float* __restrict__ conv_w) {
    const int o = blockIdx.x, b = blockIdx.y, tid = threadIdx.x;
    __shared__ float wsh[IM];
    wsh[tid] = conv_w[o * IM + tid];
    __syncthreads();

    const float* S = g_S + b * HW;
    float acc = 0.0f;
#pragma unroll 8
    for (int c = 0; c < IM; c++) acc = fmaf(wsh[c], S[c * IM + tid], acc);

    g_E[(b * IM + o) * IM + tid] = (acc >= 0.0f) ? acc : 0.2f * acc;
}

// ---------------------------------------------------------------------------
// Kernel B2: broadcast E over h into out; o==128 copies x channel 2.
// grid = (129 o, 8 b), block = 256 threads.
// ---------------------------------------------------------------------------
__global__ void __launch_bounds__(256) bcast_kernel(const float* __restrict__ x,
                                                    float* __restrict__ out) {
    const int o   = blockIdx.x;    // 0..128
    const int b   = blockIdx.y;
    const int tid = threadIdx.x;

    float4* out4 = (float4*)(out + (size_t)(b * (IM + 1) + o) * HW);

    if (o == IM) {
        const float4* src = (const float4*)(x + (size_t)b * CIN * HW + 2 * HW);
#pragma unroll
        for (int j = tid; j < HW / 4; j += 256) out4[j] = src[j];
        return;
    }

    const float4* e4 = (const float4*)(g_E + (size_t)(b * IM + o) * IM);
    float4 v = e4[tid & 31];           // one register-resident row chunk
    const int w4 = tid & 31;
    const int h0 = tid >> 5;           // 0..7
#pragma unroll
    for (int h = h0; h < IM; h += 8) out4[h * (IM / 4) + w4] = v;
}

// ---------------------------------------------------------------------------
extern "C" void kernel_launch(void* const* d_in, const int* in_sizes, int n_in,
                              void* d_out, int out_size) {
    const float* x      = (const float*)d_in[0];
    const float* conv_w = (const float*)d_in[2];
    float*       out    = (float*)d_out;

    dft_kernel<<<dim3(IM / 4, BZ), 128>>>(x);
    gemm_kernel<<<dim3(IM, BZ), IM>>>(conv_w);
    bcast_kernel<<<dim3(IM + 1, BZ), 256>>>(x, out);
}

// round 3
// speedup vs baseline: 1.3458x; 1.0664x over previous
#include <cuda_runtime.h>
#include <math.h>

#define BZ   8
#define IM   128
#define HW   (IM * IM)          // 16384
#define CIN  3

// Scratch
__device__ float4 g_WTp[32 * IM];        // WTp[i4][o] = {W[o,4i4],..,W[o,4i4+3]}
__device__ float  g_E[BZ * IM * IM];     // E[b][o][w]

// ---------------------------------------------------------------------------
// K0: pack W into (i4, o, 4) layout for coalesced GEMM reads.
// 4096 float4 outputs. grid 16 x 256.
// ---------------------------------------------------------------------------
__global__ void __launch_bounds__(256) prep_kernel(const float* __restrict__ conv_w) {
    int n  = blockIdx.x * 256 + threadIdx.x;   // 0..4095
    int o  = n & 127;
    int i4 = n >> 7;
    g_WTp[n] = ((const float4*)conv_w)[o * 32 + i4];
}

// ---------------------------------------------------------------------------
// K1: fused radix-4 column DFT magnitude + 1x1-conv GEMM + LeakyReLU.
// grid = (32 col-groups, 8 b), block = 128 threads = 4 warps = 4 columns.
// Warp wl computes S[:, w0+wl] (lane i -> outputs i, i+32, i+64, i+96),
// then all threads do E[o=t, w0..w0+3] = leakyrelu(W @ S).
// ---------------------------------------------------------------------------
__global__ void __launch_bounds__(128) dft_gemm_kernel(const float* __restrict__ x) {
    const int b    = blockIdx.y;
    const int w0   = blockIdx.x * 4;
    const int tid  = threadIdx.x;
    const int wl   = tid >> 5;
    const int lane = tid & 31;

    __shared__ float sRe[4][IM], sIm[4][IM], sS[4][IM];
    __shared__ float t128c[IM], t128s[IM], t32c[32], t32s[32];

    // Load 4 columns (both channels) as float4 rows.
    const float* xb = x + (size_t)b * CIN * HW;
    for (int k = tid; k < 256; k += 128) {
        int ch = k >> 7, h = k & 127;
        float4 v = ((const float4*)(xb + (size_t)ch * HW))[h * (IM / 4) + (w0 >> 2)];
        float (*dst)[IM] = ch ? sIm : sRe;
        dst[0][h] = v.x; dst[1][h] = v.y; dst[2][h] = v.z; dst[3][h] = v.w;
    }

    // Twiddle tables (exact, one sincosf per thread).
    {
        float s, c;
        sincosf(-6.283185307179586f * (float)tid * (1.0f / 128.0f), &s, &c);
        t128c[tid] = c; t128s[tid] = s;
        if (tid < 32) {
            sincosf(-6.283185307179586f * (float)tid * (1.0f / 32.0f), &s, &c);
            t32c[tid] = c; t32s[tid] = s;
        }
    }
    __syncthreads();

    // Radix-4 DFT: 4 phase accumulators, table twiddles (no serial chain).
    float A0r = 0, A0i = 0, A1r = 0, A1i = 0, A2r = 0, A2i = 0, A3r = 0, A3i = 0;
    const float4* r4 = (const float4*)sRe[wl];
    const float4* m4 = (const float4*)sIm[wl];

#pragma unroll
    for (int t = 0; t < 32; t++) {
        int   k = (lane * t) & 31;
        float c = t32c[k], s = t32s[k];
        float4 xr = r4[t];
        float4 xm = m4[t];
        A0r = fmaf(xr.x, c, A0r); A0r = fmaf(-xm.x, s, A0r);
        A0i = fmaf(xr.x, s, A0i); A0i = fmaf( xm.x, c, A0i);
        A1r = fmaf(xr.y, c, A1r); A1r = fmaf(-xm.y, s, A1r);
        A1i = fmaf(xr.y, s, A1i); A1i = fmaf( xm.y, c, A1i);
        A2r = fmaf(xr.z, c, A2r); A2r = fmaf(-xm.z, s, A2r);
        A2i = fmaf(xr.z, s, A2i); A2i = fmaf( xm.z, c, A2i);
        A3r = fmaf(xr.w, c, A3r); A3r = fmaf(-xm.w, s, A3r);
        A3i = fmaf(xr.w, s, A3i); A3i = fmaf( xm.w, c, A3i);
    }

    // Final twiddles W^lane, W^2lane, W^3lane (exact table reads).
    float cw = t128c[lane],            sw = t128s[lane];
    float c2 = t128c[(2 * lane) & 127], s2 = t128s[(2 * lane) & 127];
    float c3 = t128c[(3 * lane) & 127], s3 = t128s[(3 * lane) & 127];

    float T0r = A0r,                 T0i = A0i;
    float T1r = cw * A1r - sw * A1i, T1i = cw * A1i + sw * A1r;
    float T2r = c2 * A2r - s2 * A2i, T2i = c2 * A2i + s2 * A2r;
    float T3r = c3 * A3r - s3 * A3i, T3i = c3 * A3i + s3 * A3r;

    float Er = T0r + T2r, Ei = T0i + T2i;
    float Fr = T1r + T3r, Fi = T1i + T3i;
    float Gr = T0r - T2r, Gi = T0i - T2i;
    float Hr = T1r - T3r, Hi = T1i - T3i;

    float m0r = Er + Fr, m0i = Ei + Fi;
    float m2r = Er - Fr, m2i = Ei - Fi;
    float m1r = Gr + Hi, m1i = Gi - Hr;
    float m3r = Gr - Hi, m3i = Gi + Hr;

    const float inv = 1.0f / 128.0f;
    sS[wl][lane     ] = sqrtf(m0r * m0r + m0i * m0i) * inv;
    sS[wl][lane + 32] = sqrtf(m1r * m1r + m1i * m1i) * inv;
    sS[wl][lane + 64] = sqrtf(m2r * m2r + m2i * m2i) * inv;
    sS[wl][lane + 96] = sqrtf(m3r * m3r + m3i * m3i) * inv;
    __syncthreads();

    // GEMM: thread t = output channel o; 4 w-accumulators.
    float a0 = 0, a1 = 0, a2 = 0, a3 = 0;
    const float4* q0 = (const float4*)sS[0];
    const float4* q1 = (const float4*)sS[1];
    const float4* q2 = (const float4*)sS[2];
    const float4* q3 = (const float4*)sS[3];

#pragma unroll 8
    for (int i4 = 0; i4 < 32; i4++) {
        float4 wv = g_WTp[i4 * IM + tid];          // coalesced, L1/L2 resident
        float4 v0 = q0[i4], v1 = q1[i4], v2 = q2[i4], v3 = q3[i4];
        a0 = fmaf(wv.x, v0.x, a0); a0 = fmaf(wv.y, v0.y, a0);
        a0 = fmaf(wv.z, v0.z, a0); a0 = fmaf(wv.w, v0.w, a0);
        a1 = fmaf(wv.x, v1.x, a1); a1 = fmaf(wv.y, v1.y, a1);
        a1 = fmaf(wv.z, v1.z, a1); a1 = fmaf(wv.w, v1.w, a1);
        a2 = fmaf(wv.x, v2.x, a2); a2 = fmaf(wv.y, v2.y, a2);
        a2 = fmaf(wv.z, v2.z, a2); a2 = fmaf(wv.w, v2.w, a2);
        a3 = fmaf(wv.x, v3.x, a3); a3 = fmaf(wv.y, v3.y, a3);
        a3 = fmaf(wv.z, v3.z, a3); a3 = fmaf(wv.w, v3.w, a3);
    }

    float4 e;
    e.x = (a0 >= 0.0f) ? a0 : 0.2f * a0;
    e.y = (a1 >= 0.0f) ? a1 : 0.2f * a1;
    e.z = (a2 >= 0.0f) ? a2 : 0.2f * a2;
    e.w = (a3 >= 0.0f) ? a3 : 0.2f * a3;
    *(float4*)(g_E + (size_t)(b * IM + tid) * IM + w0) = e;
}

// ---------------------------------------------------------------------------
// K2: broadcast E over h into out; o==128 copies x channel 2.
// grid = (129 o, 8 b), block = 256 threads.
// ---------------------------------------------------------------------------
__global__ void __launch_bounds__(256) bcast_kernel(const float* __restrict__ x,
                                                    float* __restrict__ out) {
    const int o   = blockIdx.x;    // 0..128
    const int b   = blockIdx.y;
    const int tid = threadIdx.x;

    float4* out4 = (float4*)(out + (size_t)(b * (IM + 1) + o) * HW);

    if (o == IM) {
        const float4* src = (const float4*)(x + (size_t)b * CIN * HW + 2 * HW);
#pragma unroll
        for (int j = tid; j < HW / 4; j += 256) out4[j] = src[j];
        return;
    }

    const float4* e4 = (const float4*)(g_E + (size_t)(b * IM + o) * IM);
    float4 v = e4[tid & 31];           // register-resident row chunk
    const int w4 = tid & 31;
    const int h0 = tid >> 5;           // 0..7
#pragma unroll
    for (int h = h0; h < IM; h += 8) out4[h * (IM / 4) + w4] = v;
}

// ---------------------------------------------------------------------------
extern "C" void kernel_launch(void* const* d_in, const int* in_sizes, int n_in,
                              void* d_out, int out_size) {
    const float* x      = (const float*)d_in[0];
    const float* conv_w = (const float*)d_in[2];
    float*       out    = (float*)d_out;

    prep_kernel<<<16, 256>>>(conv_w);
    dft_gemm_kernel<<<dim3(IM / 4, BZ), 128>>>(x);
    bcast_kernel<<<dim3(IM + 1, BZ), 256>>>(x, out);
}

// round 5
// speedup vs baseline: 1.4632x; 1.0872x over previous
#include <cuda_runtime.h>
#include <math.h>

#define BZ   8
#define IM   128
#define HW   (IM * IM)          // 16384
#define CIN  3

// Dynamic smem layout (bytes):
//   [0,      65536)  sW4  : float4[32*128]  swizzled W
//   [65536,  67584)  sRe  : float[4][128]
//   [67584,  69632)  sIm  : float[4][128]
//   [69632,  71680)  sS   : float[4][128]
//   [71680,  72192)  t128c: float[128]
//   [72192,  72704)  t128s: float[128]
//   [72704,  72832)  t32c : float[32]
//   [72832,  72960)  t32s : float[32]
#define SMEM_BYTES 72960

// Scratch: E[b][o][w] = leakyrelu(W @ S)
__device__ float g_E[BZ * IM * IM];

// ---------------------------------------------------------------------------
// K1: fused radix-4 column DFT magnitude + 1x1-conv GEMM + LeakyReLU.
// grid = (32 col-groups, 8 b), block = 128 threads = 4 warps = 4 columns.
// ---------------------------------------------------------------------------
__global__ void __launch_bounds__(128) dft_gemm_kernel(const float* __restrict__ x,
                                                       const float* __restrict__ conv_w) {
    extern __shared__ char smem[];
    float4* sW4   = (float4*)(smem);
    float (*sRe)[IM] = (float (*)[IM])(smem + 65536);
    float (*sIm)[IM] = (float (*)[IM])(smem + 67584);
    float (*sS )[IM] = (float (*)[IM])(smem + 69632);
    float* t128c = (float*)(smem + 71680);
    float* t128s = (float*)(smem + 72192);
    float* t32c  = (float*)(smem + 72704);
    float* t32s  = (float*)(smem + 72832);

    const int b    = blockIdx.y;
    const int w0   = blockIdx.x * 4;
    const int tid  = threadIdx.x;
    const int wl   = tid >> 5;
    const int lane = tid & 31;

    // Stage W: coalesced loads, swizzled stores.  o = row, j = float4-in-row.
    const float4* W4 = (const float4*)conv_w;
#pragma unroll
    for (int it = 0; it < 32; it++) {
        int idx = tid + 128 * it;                      // 0..4095
        int o = idx >> 5, j = idx & 31;
        sW4[j * IM + (j ^ o)] = W4[o * 32 + j];
    }

    // Load 4 columns (both channels) as float4 rows.
    const float* xb = x + (size_t)b * CIN * HW;
    for (int k = tid; k < 256; k += 128) {
        int ch = k >> 7, h = k & 127;
        float4 v = ((const float4*)(xb + (size_t)ch * HW))[h * (IM / 4) + (w0 >> 2)];
        float (*dst)[IM] = ch ? sIm : sRe;
        dst[0][h] = v.x; dst[1][h] = v.y; dst[2][h] = v.z; dst[3][h] = v.w;
    }

    // Twiddle tables (exact, one sincosf per thread).
    {
        float s, c;
        sincosf(-6.283185307179586f * (float)tid * (1.0f / 128.0f), &s, &c);
        t128c[tid] = c; t128s[tid] = s;
        if (tid < 32) {
            sincosf(-6.283185307179586f * (float)tid * (1.0f / 32.0f), &s, &c);
            t32c[tid] = c; t32s[tid] = s;
        }
    }
    __syncthreads();

    // Radix-4 DFT: 4 phase accumulators, table twiddles.
    float A0r = 0, A0i = 0, A1r = 0, A1i = 0, A2r = 0, A2i = 0, A3r = 0, A3i = 0;
    const float4* r4 = (const float4*)sRe[wl];
    const float4* m4 = (const float4*)sIm[wl];

#pragma unroll
    for (int t = 0; t < 32; t++) {
        int   k = (lane * t) & 31;
        float c = t32c[k], s = t32s[k];
        float4 xr = r4[t];
        float4 xm = m4[t];
        A0r = fmaf(xr.x, c, A0r); A0r = fmaf(-xm.x, s, A0r);
        A0i = fmaf(xr.x, s, A0i); A0i = fmaf( xm.x, c, A0i);
        A1r = fmaf(xr.y, c, A1r); A1r = fmaf(-xm.y, s, A1r);
        A1i = fmaf(xr.y, s, A1i); A1i = fmaf( xm.y, c, A1i);
        A2r = fmaf(xr.z, c, A2r); A2r = fmaf(-xm.z, s, A2r);
        A2i = fmaf(xr.z, s, A2i); A2i = fmaf( xm.z, c, A2i);
        A3r = fmaf(xr.w, c, A3r); A3r = fmaf(-xm.w, s, A3r);
        A3i = fmaf(xr.w, s, A3i); A3i = fmaf( xm.w, c, A3i);
    }

    // Final twiddles W^lane, W^2lane, W^3lane (exact table reads).
    float cw = t128c[lane],             sw = t128s[lane];
    float c2 = t128c[(2 * lane) & 127], s2 = t128s[(2 * lane) & 127];
    float c3 = t128c[(3 * lane) & 127], s3 = t128s[(3 * lane) & 127];

    float T0r = A0r,                 T0i = A0i;
    float T1r = cw * A1r - sw * A1i, T1i = cw * A1i + sw * A1r;
    float T2r = c2 * A2r - s2 * A2i, T2i = c2 * A2i + s2 * A2r;
    float T3r = c3 * A3r - s3 * A3i, T3i = c3 * A3i + s3 * A3r;

    float Er = T0r + T2r, Ei = T0i + T2i;
    float Fr = T1r + T3r, Fi = T1i + T3i;
    float Gr = T0r - T2r, Gi = T0i - T2i;
    float Hr = T1r - T3r, Hi = T1i - T3i;

    float m0r = Er + Fr, m0i = Ei + Fi;
    float m2r = Er - Fr, m2i = Ei - Fi;
    float m1r = Gr + Hi, m1i = Gi - Hr;
    float m3r = Gr - Hi, m3i = Gi + Hr;

    const float inv = 1.0f / 128.0f;
    sS[wl][lane     ] = sqrtf(m0r * m0r + m0i * m0i) * inv;
    sS[wl][lane + 32] = sqrtf(m1r * m1r + m1i * m1i) * inv;
    sS[wl][lane + 64] = sqrtf(m2r * m2r + m2i * m2i) * inv;
    sS[wl][lane + 96] = sqrtf(m3r * m3r + m3i * m3i) * inv;
    __syncthreads();

    // GEMM: thread t = output channel o; 4 w-accumulators.
    float a0 = 0, a1 = 0, a2 = 0, a3 = 0;
    const float4* q0 = (const float4*)sS[0];
    const float4* q1 = (const float4*)sS[1];
    const float4* q2 = (const float4*)sS[2];
    const float4* q3 = (const float4*)sS[3];

#pragma unroll 8
    for (int i4 = 0; i4 < 32; i4++) {
        float4 wv = sW4[i4 * IM + (i4 ^ tid)];         // conflict-free swizzled read
        float4 v0 = q0[i4], v1 = q1[i4], v2 = q2[i4], v3 = q3[i4];
        a0 = fmaf(wv.x, v0.x, a0); a0 = fmaf(wv.y, v0.y, a0);
        a0 = fmaf(wv.z, v0.z, a0); a0 = fmaf(wv.w, v0.w, a0);
        a1 = fmaf(wv.x, v1.x, a1); a1 = fmaf(wv.y, v1.y, a1);
        a1 = fmaf(wv.z, v1.z, a1); a1 = fmaf(wv.w, v1.w, a1);
        a2 = fmaf(wv.x, v2.x, a2); a2 = fmaf(wv.y, v2.y, a2);
        a2 = fmaf(wv.z, v2.z, a2); a2 = fmaf(wv.w, v2.w, a2);
        a3 = fmaf(wv.x, v3.x, a3); a3 = fmaf(wv.y, v3.y, a3);
        a3 = fmaf(wv.z, v3.z, a3); a3 = fmaf(wv.w, v3.w, a3);
    }

    float4 e;
    e.x = (a0 >= 0.0f) ? a0 : 0.2f * a0;
    e.y = (a1 >= 0.0f) ? a1 : 0.2f * a1;
    e.z = (a2 >= 0.0f) ? a2 : 0.2f * a2;
    e.w = (a3 >= 0.0f) ? a3 : 0.2f * a3;
    *(float4*)(g_E + (size_t)(b * IM + tid) * IM + w0) = e;
}

// ---------------------------------------------------------------------------
// K2: broadcast E over h into out; o==128 copies x channel 2.
// grid = (129 o, 8 b), block = 256 threads.
// ---------------------------------------------------------------------------
__global__ void __launch_bounds__(256) bcast_kernel(const float* __restrict__ x,
                                                    float* __restrict__ out) {
    const int o   = blockIdx.x;    // 0..128
    const int b   = blockIdx.y;
    const int tid = threadIdx.x;

    float4* out4 = (float4*)(out + (size_t)(b * (IM + 1) + o) * HW);

    if (o == IM) {
        const float4* src = (const float4*)(x + (size_t)b * CIN * HW + 2 * HW);
#pragma unroll
        for (int j = tid; j < HW / 4; j += 256) out4[j] = src[j];
        return;
    }

    const float4* e4 = (const float4*)(g_E + (size_t)(b * IM + o) * IM);
    float4 v = e4[tid & 31];           // register-resident row chunk
    const int w4 = tid & 31;
    const int h0 = tid >> 5;           // 0..7
#pragma unroll
    for (int h = h0; h < IM; h += 8) out4[h * (IM / 4) + w4] = v;
}

// ---------------------------------------------------------------------------
extern "C" void kernel_launch(void* const* d_in, const int* in_sizes, int n_in,
                              void* d_out, int out_size) {
    const float* x      = (const float*)d_in[0];
    const float* conv_w = (const float*)d_in[2];
    float*       out    = (float*)d_out;

    cudaFuncSetAttribute(dft_gemm_kernel,
                         cudaFuncAttributeMaxDynamicSharedMemorySize, SMEM_BYTES);

    dft_gemm_kernel<<<dim3(IM / 4, BZ), 128, SMEM_BYTES>>>(x, conv_w);
    bcast_kernel<<<dim3(IM + 1, BZ), 256>>>(x, out);
}